// round 1
// baseline (speedup 1.0000x reference)
#include <cuda_runtime.h>

#define FULLMASK 0xFFFFFFFFu

// scratch for per-batch recon values (B = 4096 for this problem; sized with margin)
__device__ float g_recon[8192];

// One warp per batch element. Lane i owns states s1=2i+1, s2=2i+2 (states 1..64).
// State 0 is tracked redundantly (identically) on all lanes.
// Linear-space forward with power-of-two renormalization every 4 steps.
__global__ __launch_bounds__(256)
void phmm_fwd_kernel(const int* __restrict__ x,
                     const float* __restrict__ a,
                     const float* __restrict__ e,
                     int B)
{
    int gw   = (int)((blockIdx.x * blockDim.x + threadIdx.x) >> 5);
    int lane = threadIdx.x & 31;
    if (gw >= B) return;

    const float* ab  = a + (size_t)gw * 455;   // (65, 7)
    const float* ebp = e + (size_t)gw * 256;   // (64, 4)
    const int*   xb  = x + (size_t)gw * 128;   // (128,)

    const int rA = 2 * lane;        // predecessor row for s1 (also = state index 2i)
    const int rB = 2 * lane + 1;    // predecessor row for s2; own row for s1's M2I/I2I
    const int rC = 2 * lane + 2;    // own row for s2's M2I/I2I (lane31: row 64)

    // enum: M2M=0, M2I=1, M2D=2, I2M=3, I2I=4, D2M=5, D2D=6
    float TMMa = __expf(ab[rA * 7 + 0]);
    float TMDa = __expf(ab[rA * 7 + 2]);
    float TIMa = __expf(ab[rA * 7 + 3]);
    float TDMa = __expf(ab[rA * 7 + 5]);
    float TDDa = __expf(ab[rA * 7 + 6]);
    float TMMb = __expf(ab[rB * 7 + 0]);
    float TMDb = __expf(ab[rB * 7 + 2]);
    float TIMb = __expf(ab[rB * 7 + 3]);
    float TDMb = __expf(ab[rB * 7 + 5]);
    float TDDb = __expf(ab[rB * 7 + 6]);
    float TMI1 = __expf(ab[rB * 7 + 1]);
    float TII1 = __expf(ab[rB * 7 + 4]);
    float TMI2 = __expf(ab[rC * 7 + 1]);
    float TII2 = __expf(ab[rC * 7 + 4]);
    float T0MI = __expf(ab[1]);             // a[0, M2I]
    float T0II = __expf(ab[4]);             // a[0, I2I]
    float TMMf = __expf(ab[64 * 7 + 0]);    // final combine (lane 31 uses)
    float TIMf = __expf(ab[64 * 7 + 3]);
    float TDMf = __expf(ab[64 * 7 + 5]);

    // emissions: state s1 uses e row 2i, state s2 uses e row 2i+1
    float4 e1r = *reinterpret_cast<const float4*>(ebp + rA * 4);
    float4 e2r = *reinterpret_cast<const float4*>(ebp + rB * 4);
    float E10 = __expf(e1r.x), E11 = __expf(e1r.y), E12 = __expf(e1r.z), E13 = __expf(e1r.w);
    float E20 = __expf(e2r.x), E21 = __expf(e2r.y), E22 = __expf(e2r.z), E23 = __expf(e2r.w);

    // sequence, 4 symbols per lane, broadcast via shuffle
    int xr0 = xb[lane], xr1 = xb[32 + lane], xr2 = xb[64 + lane], xr3 = xb[96 + lane];

    // state (linear space). FM0/FI0 = state 0, tracked identically on all lanes.
    float FM0 = 1.f, FI0 = 0.f;                 // fM0[0]=0 (log) -> 1; NEG -> 0
    float FM1 = 0.f, FM2 = 0.f, FI1 = 0.f, FI2 = 0.f, FD1, FD2;
    int   expAcc = 0;

    // ---- initial delete chain from fM0 (only state 0 carries mass) ----
    {
        float pN = (lane == 0) ? 1.f : 0.f;     // fM0[2i]
        float A1 = TMDa * pN, R1 = TDDa;
        float A2 = 0.f,       R2 = TDDb;        // fM0[2i+1] = 0
        float Au = fmaf(R2, A1, A2), Ru = R2 * R1;
        #pragma unroll
        for (int d = 1; d < 32; d <<= 1) {
            float Ap = __shfl_up_sync(FULLMASK, Au, d);
            float Rp = __shfl_up_sync(FULLMASK, Ru, d);
            if (lane >= d) { Au = fmaf(Ru, Ap, Au); Ru *= Rp; }
        }
        float Pex = __shfl_up_sync(FULLMASK, Au, 1);
        if (lane == 0) Pex = 0.f;
        FD1 = fmaf(R1, Pex, A1);
        FD2 = Au;
    }

    // ---- main time loop: L = 128 = 4 groups of 32, renorm every 4 steps ----
    for (int j = 0; j < 4; j++) {
        int xw = (j == 0) ? xr0 : (j == 1) ? xr1 : (j == 2) ? xr2 : xr3;
        for (int i = 0; i < 32; i += 4) {
            #pragma unroll
            for (int s = 0; s < 4; s++) {
                int xl = __shfl_sync(FULLMASK, xw, i + s);

                // predecessors (OLD values at state 2i = lane i-1's s2; lane0 -> state 0)
                float pFM = __shfl_up_sync(FULLMASK, FM2, 1);
                float pFI = __shfl_up_sync(FULLMASK, FI2, 1);
                float pFD = __shfl_up_sync(FULLMASK, FD2, 1);
                if (lane == 0) { pFM = FM0; pFI = FI0; pFD = 0.f; }  // fD[0] = 0

                float es1 = (xl == 0) ? E10 : (xl == 1) ? E11 : (xl == 2) ? E12 : E13;
                float es2 = (xl == 0) ? E20 : (xl == 1) ? E21 : (xl == 2) ? E22 : E23;

                float nFM1 = es1 * fmaf(TMMa, pFM, fmaf(TIMa, pFI, TDMa * pFD));
                float nFM2 = es2 * fmaf(TMMb, FM1, fmaf(TIMb, FI1, TDMb * FD1));

                float nFI0 = 0.25f * fmaf(T0MI, FM0, T0II * FI0);
                float nFI1 = 0.25f * fmaf(TMI1, FM1, TII1 * FI1);
                float nFI2 = 0.25f * fmaf(TMI2, FM2, TII2 * FI2);

                // delete chain from NEW fM: FD[k] = A[k] + R[k]*FD[k-1]
                float pN = __shfl_up_sync(FULLMASK, nFM2, 1);
                if (lane == 0) pN = 0.f;        // fM_new[0] = 0 for l >= 1
                float A1 = TMDa * pN,   R1 = TDDa;
                float A2 = TMDb * nFM1, R2 = TDDb;
                float Au = fmaf(R2, A1, A2), Ru = R2 * R1;
                #pragma unroll
                for (int d = 1; d < 32; d <<= 1) {
                    float Ap = __shfl_up_sync(FULLMASK, Au, d);
                    float Rp = __shfl_up_sync(FULLMASK, Ru, d);
                    if (lane >= d) { Au = fmaf(Ru, Ap, Au); Ru *= Rp; }
                }
                float Pex = __shfl_up_sync(FULLMASK, Au, 1);
                if (lane == 0) Pex = 0.f;
                FD1 = fmaf(R1, Pex, A1);
                FD2 = Au;

                FM1 = nFM1; FM2 = nFM2;
                FI0 = nFI0; FI1 = nFI1; FI2 = nFI2;
                FM0 = 0.f;
            }

            // ---- power-of-two renormalization (exponent-only, ALU) ----
            float m = fmaxf(fmaxf(fmaxf(FM1, FM2), fmaxf(FI1, FI2)),
                            fmaxf(fmaxf(FD1, FD2), FI0));
            #pragma unroll
            for (int d = 16; d > 0; d >>= 1)
                m = fmaxf(m, __shfl_xor_sync(FULLMASK, m, d));
            int ebits = (__float_as_int(m) >> 23) & 255;
            ebits = max(1, min(253, ebits));
            float scale = __int_as_float((254 - ebits) << 23);   // 2^(127 - ebits)
            expAcc += ebits - 127;
            FM1 *= scale; FM2 *= scale;
            FI0 *= scale; FI1 *= scale; FI2 *= scale;
            FD1 *= scale; FD2 *= scale;
        }
    }

    if (lane == 31) {
        // final = logsumexp(fM[64]+a[64,M2M], fI[64]+a[64,I2M], fD[64]+a[64,D2M])
        float S = fmaf(TMMf, FM2, fmaf(TIMf, FI2, TDMf * FD2));
        S = fmaxf(S, 1e-37f);
        g_recon[gw] = -(logf(S) + (float)expAcc * 0.69314718055994530942f);
    }
}

// KLD + deterministic mean reduction (single block -> fixed summation order)
__global__ void reduce_kernel(const float* __restrict__ mus,
                              const float* __restrict__ lvs,
                              float* __restrict__ out, int B, int E)
{
    int t = threadIdx.x;
    float s = 0.f;
    for (int b = t; b < B; b += (int)blockDim.x) {
        const float* mu = mus + (size_t)b * E;
        const float* lv = lvs + (size_t)b * E;
        float k = 0.f;
        for (int j = 0; j < E; j++) {
            float m_ = mu[j], v = lv[j];
            k += 1.f + v - m_ * m_ - __expf(v);
        }
        s += g_recon[b] - 0.5f * k;
    }
    __shared__ float sh[1024];
    sh[t] = s;
    __syncthreads();
    for (int d = 512; d > 0; d >>= 1) {
        if (t < d) sh[t] += sh[t + d];
        __syncthreads();
    }
    if (t == 0) out[0] = sh[0] / (float)B;
}

extern "C" void kernel_launch(void* const* d_in, const int* in_sizes, int n_in,
                              void* d_out, int out_size)
{
    const int*   x   = (const int*)d_in[0];     // (B, 128) int32
    const float* a   = (const float*)d_in[1];   // (B, 65, 7)
    const float* e   = (const float*)d_in[2];   // (B, 64, 4)
    const float* mus = (const float*)d_in[3];   // (B, E)
    const float* lvs = (const float*)d_in[4];   // (B, E)

    int B = in_sizes[1] / 455;                  // (K+1)*7 = 455
    if (B > 8192) B = 8192;                     // scratch bound (B=4096 here)
    int E = in_sizes[3] / B;

    int threads = 256;
    int blocks  = (B * 32 + threads - 1) / threads;
    phmm_fwd_kernel<<<blocks, threads>>>(x, a, e, B);
    reduce_kernel<<<1, 1024>>>(mus, lvs, (float*)d_out, B, E);
}

// round 2
// speedup vs baseline: 1.9511x; 1.9511x over previous
#include <cuda_runtime.h>

#define FULLMASK 0xFFFFFFFFu

__device__ float g_recon[8192];

// ---- f32x2 packed helpers (FFMA2/FMUL2 only reachable via PTX) ----
__device__ __forceinline__ unsigned long long pk2(float lo, float hi) {
    unsigned long long r;
    asm("mov.b64 %0, {%1, %2};" : "=l"(r) : "f"(lo), "f"(hi));
    return r;
}
__device__ __forceinline__ void upk2(unsigned long long v, float& lo, float& hi) {
    asm("mov.b64 {%0, %1}, %2;" : "=f"(lo), "=f"(hi) : "l"(v));
}
__device__ __forceinline__ unsigned long long fma2(unsigned long long a,
                                                   unsigned long long b,
                                                   unsigned long long c) {
    unsigned long long d;
    asm("fma.rn.f32x2 %0, %1, %2, %3;" : "=l"(d) : "l"(a), "l"(b), "l"(c));
    return d;
}
__device__ __forceinline__ unsigned long long mul2(unsigned long long a,
                                                   unsigned long long b) {
    unsigned long long d;
    asm("mul.rn.f32x2 %0, %1, %2;" : "=l"(d) : "l"(a), "l"(b));
    return d;
}

// One warp per batch element. Lane i owns states 2i+1, 2i+2.
// Linear space + power-of-two renorm every 8 steps.
__global__ __launch_bounds__(128)
void phmm_fwd_kernel(const int* __restrict__ x,
                     const float* __restrict__ a,
                     const float* __restrict__ e,
                     const float* __restrict__ mus,
                     const float* __restrict__ lvs,
                     int B, int E)
{
    int gw   = (int)((blockIdx.x * blockDim.x + threadIdx.x) >> 5);
    int lane = threadIdx.x & 31;
    if (gw >= B) return;

    // ---- KLD for this batch (hidden under startup latency) ----
    float kterm = 0.f;
    if (lane < E) {
        float m_ = mus[(size_t)gw * E + lane];
        float v  = lvs[(size_t)gw * E + lane];
        kterm = 1.f + v - m_ * m_ - __expf(v);
    }
    #pragma unroll
    for (int d = 16; d > 0; d >>= 1) kterm += __shfl_xor_sync(FULLMASK, kterm, d);

    const float* ab  = a + (size_t)gw * 455;   // (65, 7)
    const float* ebp = e + (size_t)gw * 256;   // (64, 4)
    const int*   xb  = x + (size_t)gw * 128;

    const int rA = 2 * lane;
    const int rB = 2 * lane + 1;
    const int rC = 2 * lane + 2;

    // enum: M2M=0, M2I=1, M2D=2, I2M=3, I2I=4, D2M=5, D2D=6
    float TMMa = __expf(ab[rA * 7 + 0]);
    float TMDa = __expf(ab[rA * 7 + 2]);
    float TIMa = __expf(ab[rA * 7 + 3]);
    float TDMa = __expf(ab[rA * 7 + 5]);
    float TDDa = __expf(ab[rA * 7 + 6]);
    float TMMb = __expf(ab[rB * 7 + 0]);
    float TMDb = __expf(ab[rB * 7 + 2]);
    float TIMb = __expf(ab[rB * 7 + 3]);
    float TDMb = __expf(ab[rB * 7 + 5]);
    float TDDb = __expf(ab[rB * 7 + 6]);
    float TMI1q = 0.25f * __expf(ab[rB * 7 + 1]);
    float TII1q = 0.25f * __expf(ab[rB * 7 + 4]);
    float TMI2q = 0.25f * __expf(ab[rC * 7 + 1]);
    float TII2q = 0.25f * __expf(ab[rC * 7 + 4]);
    float T0MIq = 0.25f * __expf(ab[1]);
    float T0IIq = 0.25f * __expf(ab[4]);
    float TMMf = __expf(ab[64 * 7 + 0]);
    float TIMf = __expf(ab[64 * 7 + 3]);
    float TDMf = __expf(ab[64 * 7 + 5]);

    float4 e1r = *reinterpret_cast<const float4*>(ebp + rA * 4);
    float4 e2r = *reinterpret_cast<const float4*>(ebp + rB * 4);
    unsigned long long E0p = pk2(__expf(e1r.x), __expf(e2r.x));
    unsigned long long E1p = pk2(__expf(e1r.y), __expf(e2r.y));
    unsigned long long E2p = pk2(__expf(e1r.z), __expf(e2r.z));
    unsigned long long E3p = pk2(__expf(e1r.w), __expf(e2r.w));

    unsigned long long TMM12 = pk2(TMMa, TMMb);
    unsigned long long TIM12 = pk2(TIMa, TIMb);
    unsigned long long TDM12 = pk2(TDMa, TDMb);
    unsigned long long TMI12 = pk2(TMI1q, TMI2q);
    unsigned long long TII12 = pk2(TII1q, TII2q);

    // ---- time-invariant scan ratio prefixes (R entering each scan level) ----
    float Rcur = TDDb * TDDa;
    float Rl1 = Rcur;
    { float Rp = __shfl_up_sync(FULLMASK, Rcur, 1);  if (lane >= 1)  Rcur *= Rp; }
    float Rl2 = Rcur;
    { float Rp = __shfl_up_sync(FULLMASK, Rcur, 2);  if (lane >= 2)  Rcur *= Rp; }
    float Rl4 = Rcur;
    { float Rp = __shfl_up_sync(FULLMASK, Rcur, 4);  if (lane >= 4)  Rcur *= Rp; }
    float Rl8 = Rcur;
    { float Rp = __shfl_up_sync(FULLMASK, Rcur, 8);  if (lane >= 8)  Rcur *= Rp; }
    float Rl16 = Rcur;

    // ---- state init + initial delete chain (only state 0 has mass) ----
    unsigned long long FM12 = 0ull, FI12 = 0ull;
    float FI0 = 0.f, FM0 = 1.f;
    float FD1, FD2, pNprev, Pexprev;
    int expAcc = 0;
    {
        float A1 = (lane == 0) ? TMDa : 0.f;
        float Au = TDDb * A1;                       // A2 = 0
        float Ap;
        Ap = __shfl_up_sync(FULLMASK, Au, 1);  Au = (lane >= 1)  ? fmaf(Rl1,  Ap, Au) : Au;
        Ap = __shfl_up_sync(FULLMASK, Au, 2);  Au = (lane >= 2)  ? fmaf(Rl2,  Ap, Au) : Au;
        Ap = __shfl_up_sync(FULLMASK, Au, 4);  Au = (lane >= 4)  ? fmaf(Rl4,  Ap, Au) : Au;
        Ap = __shfl_up_sync(FULLMASK, Au, 8);  Au = (lane >= 8)  ? fmaf(Rl8,  Ap, Au) : Au;
        Ap = __shfl_up_sync(FULLMASK, Au, 16); Au = (lane >= 16) ? fmaf(Rl16, Ap, Au) : Au;
        float Pex = __shfl_up_sync(FULLMASK, Au, 1);
        if (lane == 0) Pex = 0.f;
        FD1 = fmaf(TDDa, Pex, A1);
        FD2 = Au;
        Pexprev = Pex;                              // old fD at state 2i
        pNprev  = (lane == 0) ? 1.f : 0.f;          // old fM at state 2i
    }

    const int4* xv = reinterpret_cast<const int4*>(xb);

    // ---- main loop: 8 groups x 16 steps, renorm every 8 steps ----
    for (int w = 0; w < 8; w++) {
        int4 q0 = xv[4 * w + 0], q1 = xv[4 * w + 1];
        int4 q2 = xv[4 * w + 2], q3 = xv[4 * w + 3];
        unsigned pw =
              (unsigned)q0.x        | ((unsigned)q0.y << 2)  | ((unsigned)q0.z << 4)  | ((unsigned)q0.w << 6)
            | ((unsigned)q1.x << 8) | ((unsigned)q1.y << 10) | ((unsigned)q1.z << 12) | ((unsigned)q1.w << 14)
            | ((unsigned)q2.x << 16)| ((unsigned)q2.y << 18) | ((unsigned)q2.z << 20) | ((unsigned)q2.w << 22)
            | ((unsigned)q3.x << 24)| ((unsigned)q3.y << 26) | ((unsigned)q3.z << 28) | ((unsigned)q3.w << 30);

        #pragma unroll
        for (int s = 0; s < 16; s++) {
            int sym = (int)((pw >> (2 * s)) & 3u);

            float FM1, FM2; upk2(FM12, FM1, FM2);
            float FI1, FI2; upk2(FI12, FI1, FI2);

            float pFI = __shfl_up_sync(FULLMASK, FI2, 1);
            if (lane == 0) pFI = FI0;

            unsigned long long es12 = (sym & 2) ? ((sym & 1) ? E3p : E2p)
                                                : ((sym & 1) ? E1p : E0p);
            unsigned long long prevM = pk2(pNprev,  FM1);
            unsigned long long prevI = pk2(pFI,     FI1);
            unsigned long long prevD = pk2(Pexprev, FD1);

            unsigned long long acc = fma2(TIM12, prevI, mul2(TDM12, prevD));
            acc = fma2(TMM12, prevM, acc);
            unsigned long long nFM12 = mul2(es12, acc);
            float nFM1, nFM2; upk2(nFM12, nFM1, nFM2);

            FI0 = fmaf(T0MIq, FM0, T0IIq * FI0);
            FM0 = 0.f;
            unsigned long long nFI12 = fma2(TMI12, FM12, mul2(TII12, FI12));

            // delete chain on NEW fM
            float pN = __shfl_up_sync(FULLMASK, nFM2, 1);
            if (lane == 0) pN = 0.f;
            float A1 = TMDa * pN;
            float A2 = TMDb * nFM1;
            float Au = fmaf(TDDb, A1, A2);
            float Ap;
            Ap = __shfl_up_sync(FULLMASK, Au, 1);  Au = (lane >= 1)  ? fmaf(Rl1,  Ap, Au) : Au;
            Ap = __shfl_up_sync(FULLMASK, Au, 2);  Au = (lane >= 2)  ? fmaf(Rl2,  Ap, Au) : Au;
            Ap = __shfl_up_sync(FULLMASK, Au, 4);  Au = (lane >= 4)  ? fmaf(Rl4,  Ap, Au) : Au;
            Ap = __shfl_up_sync(FULLMASK, Au, 8);  Au = (lane >= 8)  ? fmaf(Rl8,  Ap, Au) : Au;
            Ap = __shfl_up_sync(FULLMASK, Au, 16); Au = (lane >= 16) ? fmaf(Rl16, Ap, Au) : Au;
            float Pex = __shfl_up_sync(FULLMASK, Au, 1);
            if (lane == 0) Pex = 0.f;
            FD1 = fmaf(TDDa, Pex, A1);
            FD2 = Au;
            pNprev  = pN;      // next step's old-fM predecessor
            Pexprev = Pex;     // next step's old-fD predecessor
            FM12 = nFM12;
            FI12 = nFI12;

            if (s == 7 || s == 15) {   // renorm every 8 steps
                float fm1, fm2, fi1, fi2;
                upk2(FM12, fm1, fm2); upk2(FI12, fi1, fi2);
                float m = fmaxf(fmaxf(fmaxf(fm1, fm2), fmaxf(fi1, fi2)),
                                fmaxf(fmaxf(FD1, FD2), FI0));
                #pragma unroll
                for (int d = 16; d > 0; d >>= 1)
                    m = fmaxf(m, __shfl_xor_sync(FULLMASK, m, d));
                int eb = (__float_as_int(m) >> 23) & 255;
                eb = max(1, min(253, eb));
                float scale = __int_as_float((254 - eb) << 23);   // 2^(127-eb)
                expAcc += eb - 127;
                unsigned long long sp = pk2(scale, scale);
                FM12 = mul2(FM12, sp);
                FI12 = mul2(FI12, sp);
                FI0 *= scale; FD1 *= scale; FD2 *= scale;
                pNprev *= scale; Pexprev *= scale;
            }
        }
    }

    if (lane == 31) {
        float fm1, fm2, fi1, fi2;
        upk2(FM12, fm1, fm2); upk2(FI12, fi1, fi2);
        float S = fmaf(TMMf, fm2, fmaf(TIMf, fi2, TDMf * FD2));
        S = fmaxf(S, 1e-37f);
        g_recon[gw] = -(logf(S) + (float)expAcc * 0.69314718055994530942f)
                      - 0.5f * kterm;
    }
}

// deterministic mean of g_recon[0..B)
__global__ void reduce_kernel(float* __restrict__ out, int B)
{
    int t = threadIdx.x;
    float s = 0.f;
    for (int b = t; b < B; b += 1024) s += g_recon[b];
    __shared__ float sh[1024];
    sh[t] = s;
    __syncthreads();
    for (int d = 512; d > 0; d >>= 1) {
        if (t < d) sh[t] += sh[t + d];
        __syncthreads();
    }
    if (t == 0) out[0] = sh[0] / (float)B;
}

extern "C" void kernel_launch(void* const* d_in, const int* in_sizes, int n_in,
                              void* d_out, int out_size)
{
    const int*   x   = (const int*)d_in[0];     // (B, 128) int32
    const float* a   = (const float*)d_in[1];   // (B, 65, 7)
    const float* e   = (const float*)d_in[2];   // (B, 64, 4)
    const float* mus = (const float*)d_in[3];   // (B, E)
    const float* lvs = (const float*)d_in[4];   // (B, E)

    int B = in_sizes[1] / 455;
    if (B > 8192) B = 8192;
    int E = in_sizes[3] / B;

    int threads = 128;                          // 4 warps/block
    int blocks  = (B * 32 + threads - 1) / threads;
    phmm_fwd_kernel<<<blocks, threads>>>(x, a, e, mus, lvs, B, E);
    reduce_kernel<<<1, 1024>>>((float*)d_out, B);
}

// round 5
// speedup vs baseline: 2.4565x; 1.2591x over previous
#include <cuda_runtime.h>

#define FULLMASK 0xFFFFFFFFu
typedef unsigned long long u64;

__device__ float g_recon[8192];

// ---- f32x2 packed helpers ----
__device__ __forceinline__ u64 pk2(float lo, float hi) {
    u64 r; asm("mov.b64 %0, {%1, %2};" : "=l"(r) : "f"(lo), "f"(hi)); return r;
}
__device__ __forceinline__ void upk2(u64 v, float& lo, float& hi) {
    asm("mov.b64 {%0, %1}, %2;" : "=f"(lo), "=f"(hi) : "l"(v));
}
__device__ __forceinline__ u64 fma2(u64 a, u64 b, u64 c) {
    u64 d; asm("fma.rn.f32x2 %0, %1, %2, %3;" : "=l"(d) : "l"(a), "l"(b), "l"(c)); return d;
}
__device__ __forceinline__ u64 mul2(u64 a, u64 b) {
    u64 d; asm("mul.rn.f32x2 %0, %1, %2;" : "=l"(d) : "l"(a), "l"(b)); return d;
}

// Two batches per warp (16-lane segments). Lane sl (0..15) owns states 4sl+1..4sl+4.
// Linear space + power-of-two renorm every 8 steps. KLD folded into load phase.
__global__ __launch_bounds__(128, 4)
void phmm_fwd_kernel(const int* __restrict__ x,
                     const float* __restrict__ a,
                     const float* __restrict__ e,
                     const float* __restrict__ mus,
                     const float* __restrict__ lvs,
                     int B, int E)
{
    const int warp  = (int)((blockIdx.x * blockDim.x + threadIdx.x) >> 5);
    const int lane  = threadIdx.x & 31;
    const int sl    = lane & 15;
    const int batch = 2 * warp + (lane >> 4);
    const int bc    = (batch < B) ? batch : (B - 1);   // clamp; final write guarded

    // ---- KLD for this segment's batch (hidden under startup latency) ----
    float kterm = 0.f;
    if (sl < E) {
        float m_ = mus[(size_t)bc * E + sl];
        float v  = lvs[(size_t)bc * E + sl];
        kterm = 1.f + v - m_ * m_ - __expf(v);
    }
    #pragma unroll
    for (int d = 8; d > 0; d >>= 1) kterm += __shfl_xor_sync(FULLMASK, kterm, d, 16);

    const float* ab  = a + (size_t)bc * 455;   // (65, 7)
    const float* ebp = e + (size_t)bc * 256;   // (64, 4)
    const int r0 = sl * 4;

    // enum: M2M=0, M2I=1, M2D=2, I2M=3, I2I=4, D2M=5, D2D=6
    float TMM[4], TIM[4], TDM[4], TMD[4], TDD[4], TMIq[4], TIIq[4];
    #pragma unroll
    for (int c = 0; c < 4; c++) {
        const float* rw = ab + (r0 + c) * 7;
        TMM[c] = __expf(rw[0]);
        TMD[c] = __expf(rw[2]);
        TIM[c] = __expf(rw[3]);
        TDM[c] = __expf(rw[5]);
        TDD[c] = __expf(rw[6]);
        const float* rwn = ab + (r0 + c + 1) * 7;
        TMIq[c] = 0.25f * __expf(rwn[1]);
        TIIq[c] = 0.25f * __expf(rwn[4]);
    }
    // predecessor-I recurrence coeffs (row 4sl); for sl==0 this tracks fI[0]
    float TMIqm = 0.25f * __expf(ab[r0 * 7 + 1]);
    float TIIqm = 0.25f * __expf(ab[r0 * 7 + 4]);
    // finals (used by sl==15)
    float TMMf = __expf(ab[64 * 7 + 0]);
    float TIMf = __expf(ab[64 * 7 + 3]);
    float TDMf = __expf(ab[64 * 7 + 5]);

    // boundary: fD[0] == 0 always -> zero its multipliers on segment lane 0
    if (sl == 0) { TDM[0] = 0.f; TDD[0] = 0.f; }

    u64 TMM01 = pk2(TMM[0], TMM[1]), TMM23 = pk2(TMM[2], TMM[3]);
    u64 TIM01 = pk2(TIM[0], TIM[1]), TIM23 = pk2(TIM[2], TIM[3]);
    u64 TDM01 = pk2(TDM[0], TDM[1]), TDM23 = pk2(TDM[2], TDM[3]);
    u64 TMI01 = pk2(TMIq[0], TMIq[1]), TMI23 = pk2(TMIq[2], TMIq[3]);
    u64 TII01 = pk2(TIIq[0], TIIq[1]), TII23 = pk2(TIIq[2], TIIq[3]);

    // emissions: state 4sl+1+c uses e row r0+c
    float4 er0 = *reinterpret_cast<const float4*>(ebp + (r0 + 0) * 4);
    float4 er1 = *reinterpret_cast<const float4*>(ebp + (r0 + 1) * 4);
    float4 er2 = *reinterpret_cast<const float4*>(ebp + (r0 + 2) * 4);
    float4 er3 = *reinterpret_cast<const float4*>(ebp + (r0 + 3) * 4);
    u64 E0_01 = pk2(__expf(er0.x), __expf(er1.x)), E0_23 = pk2(__expf(er2.x), __expf(er3.x));
    u64 E1_01 = pk2(__expf(er0.y), __expf(er1.y)), E1_23 = pk2(__expf(er2.y), __expf(er3.y));
    u64 E2_01 = pk2(__expf(er0.z), __expf(er1.z)), E2_23 = pk2(__expf(er2.z), __expf(er3.z));
    u64 E3_01 = pk2(__expf(er0.w), __expf(er1.w)), E3_23 = pk2(__expf(er2.w), __expf(er3.w));

    // scan ratio prefixes over the 16-lane segment (zeroed below each level)
    float Rc = TDD[3] * TDD[2] * TDD[1] * TDD[0], Rp;
    float Rl1 = (sl >= 1) ? Rc : 0.f;
    Rp = __shfl_up_sync(FULLMASK, Rc, 1, 16); if (sl >= 1) Rc *= Rp;
    float Rl2 = (sl >= 2) ? Rc : 0.f;
    Rp = __shfl_up_sync(FULLMASK, Rc, 2, 16); if (sl >= 2) Rc *= Rp;
    float Rl4 = (sl >= 4) ? Rc : 0.f;
    Rp = __shfl_up_sync(FULLMASK, Rc, 4, 16); if (sl >= 4) Rc *= Rp;
    float Rl8 = (sl >= 8) ? Rc : 0.f;

    // symbol packing: lanes sl<8 hold the 16-symbol word for group sl
    unsigned word = 0;
    if (sl < 8) {
        const int4* xv = reinterpret_cast<const int4*>(x + (size_t)bc * 128) + sl * 4;
        int4 q0 = xv[0], q1 = xv[1], q2 = xv[2], q3 = xv[3];
        word =  (unsigned)q0.x        | ((unsigned)q0.y << 2)  | ((unsigned)q0.z << 4)  | ((unsigned)q0.w << 6)
             | ((unsigned)q1.x << 8)  | ((unsigned)q1.y << 10) | ((unsigned)q1.z << 12) | ((unsigned)q1.w << 14)
             | ((unsigned)q2.x << 16) | ((unsigned)q2.y << 18) | ((unsigned)q2.z << 20) | ((unsigned)q2.w << 22)
             | ((unsigned)q3.x << 24) | ((unsigned)q3.y << 26) | ((unsigned)q3.z << 28) | ((unsigned)q3.w << 30);
    }

    // ---- state init + initial delete chain (only state 0 carries mass) ----
    u64 FMp01 = 0ull, FMp23 = 0ull, FIp01 = 0ull, FIp23 = 0ull;
    float FD1, FD2, FD3, FD4;
    float pFI = 0.f;                         // fI[4sl] (sl==0: fI[0])
    float pNprev = (sl == 0) ? 1.f : 0.f;    // fM[4sl] (t=0: fM0[0]=1)
    float Pexprev;                           // fD[4sl]
    int expAcc = 0;
    {
        float A1 = (sl == 0) ? TMD[0] : 0.f; // A2=A3=A4=0
        float Au = TDD[3] * (TDD[2] * (TDD[1] * A1)), Ap;
        Ap = __shfl_up_sync(FULLMASK, Au, 1, 16); Au = fmaf(Rl1, Ap, Au);
        Ap = __shfl_up_sync(FULLMASK, Au, 2, 16); Au = fmaf(Rl2, Ap, Au);
        Ap = __shfl_up_sync(FULLMASK, Au, 4, 16); Au = fmaf(Rl4, Ap, Au);
        Ap = __shfl_up_sync(FULLMASK, Au, 8, 16); Au = fmaf(Rl8, Ap, Au);
        float Pex = __shfl_up_sync(FULLMASK, Au, 1, 16);
        FD1 = fmaf(TDD[0], Pex, A1);         // TDD[0]=0 on sl==0 -> Pex garbage ok
        FD2 = TDD[1] * FD1;
        FD3 = TDD[2] * FD2;
        FD4 = Au;
        Pexprev = Pex;                       // sl==0 garbage killed by TDM[0]=0
    }

    // ---- main loop: 8 groups x 16 steps, renorm every 8 steps ----
    for (int w = 0; w < 8; w++) {
        unsigned pw = __shfl_sync(FULLMASK, word, w, 16);
        #pragma unroll
        for (int s = 0; s < 16; s++) {
            unsigned b1 = (pw >> (2 * s + 1)) & 1u;
            unsigned b0 = (pw >> (2 * s)) & 1u;
            u64 es01 = b1 ? (b0 ? E3_01 : E2_01) : (b0 ? E1_01 : E0_01);
            u64 es23 = b1 ? (b0 ? E3_23 : E2_23) : (b0 ? E1_23 : E0_23);

            float FM1, FM2, FM3, FM4, FI1, FI2, FI3, FI4;
            upk2(FMp01, FM1, FM2); upk2(FMp23, FM3, FM4);
            upk2(FIp01, FI1, FI2); upk2(FIp23, FI3, FI4);

            u64 prevM01 = pk2(pNprev, FM1),  prevM23 = pk2(FM2, FM3);
            u64 prevI01 = pk2(pFI, FI1),     prevI23 = pk2(FI2, FI3);
            u64 prevD01 = pk2(Pexprev, FD1), prevD23 = pk2(FD2, FD3);

            u64 t01 = fma2(TMM01, prevM01, fma2(TIM01, prevI01, mul2(TDM01, prevD01)));
            u64 t23 = fma2(TMM23, prevM23, fma2(TIM23, prevI23, mul2(TDM23, prevD23)));
            u64 nM01 = mul2(es01, t01), nM23 = mul2(es23, t23);
            float nFM1, nFM2, nFM3, nFM4;
            upk2(nM01, nFM1, nFM2); upk2(nM23, nFM3, nFM4);

            // insert states (own rows) + predecessor-I local recurrence
            u64 nI01 = fma2(TMI01, FMp01, mul2(TII01, FIp01));
            u64 nI23 = fma2(TMI23, FMp23, mul2(TII23, FIp23));
            pFI = fmaf(TMIqm, pNprev, TIIqm * pFI);

            // delete chain on NEW fM (4-level segment scan)
            float pN = __shfl_up_sync(FULLMASK, nFM4, 1, 16);
            if (sl == 0) pN = 0.f;           // fM_new[0] = 0 for l >= 1
            float A1 = TMD[0] * pN, A2 = TMD[1] * nFM1;
            float A3 = TMD[2] * nFM2, A4 = TMD[3] * nFM3;
            float Au = fmaf(TDD[3], fmaf(TDD[2], fmaf(TDD[1], A1, A2), A3), A4);
            float Ap;
            Ap = __shfl_up_sync(FULLMASK, Au, 1, 16); Au = fmaf(Rl1, Ap, Au);
            Ap = __shfl_up_sync(FULLMASK, Au, 2, 16); Au = fmaf(Rl2, Ap, Au);
            Ap = __shfl_up_sync(FULLMASK, Au, 4, 16); Au = fmaf(Rl4, Ap, Au);
            Ap = __shfl_up_sync(FULLMASK, Au, 8, 16); Au = fmaf(Rl8, Ap, Au);
            float Pex = __shfl_up_sync(FULLMASK, Au, 1, 16);
            FD1 = fmaf(TDD[0], Pex, A1);
            FD2 = fmaf(TDD[1], FD1, A2);
            FD3 = fmaf(TDD[2], FD2, A3);
            FD4 = Au;

            pNprev = pN; Pexprev = Pex;
            FMp01 = nM01; FMp23 = nM23;
            FIp01 = nI01; FIp23 = nI23;

            if (s == 7 || s == 15) {   // renorm every 8 steps
                float m1, m2, m3, m4, i1, i2, i3, i4;
                upk2(FMp01, m1, m2); upk2(FMp23, m3, m4);
                upk2(FIp01, i1, i2); upk2(FIp23, i3, i4);
                float m = fmaxf(fmaxf(fmaxf(m1, m2), fmaxf(m3, m4)),
                                fmaxf(fmaxf(i1, i2), fmaxf(i3, i4)));
                m = fmaxf(m, fmaxf(fmaxf(FD1, FD2), fmaxf(FD3, FD4)));
                m = fmaxf(m, pFI);
                #pragma unroll
                for (int d = 8; d > 0; d >>= 1)
                    m = fmaxf(m, __shfl_xor_sync(FULLMASK, m, d, 16));
                int eb = (__float_as_int(m) >> 23) & 255;
                eb = max(1, min(253, eb));
                float sc = __int_as_float((254 - eb) << 23);  // 2^(127-eb)
                expAcc += eb - 127;
                u64 sp = pk2(sc, sc);
                FMp01 = mul2(FMp01, sp); FMp23 = mul2(FMp23, sp);
                FIp01 = mul2(FIp01, sp); FIp23 = mul2(FIp23, sp);
                FD1 *= sc; FD2 *= sc; FD3 *= sc; FD4 *= sc;
                pFI *= sc; pNprev *= sc; Pexprev *= sc;
            }
        }
    }

    if (sl == 15 && batch < B) {
        float FM4, FI4, d_;
        upk2(FMp23, d_, FM4);
        upk2(FIp23, d_, FI4);
        float S = fmaf(TMMf, FM4, fmaf(TIMf, FI4, TDMf * FD4));
        S = fmaxf(S, 1e-37f);
        g_recon[batch] = -(logf(S) + (float)expAcc * 0.69314718055994530942f)
                         - 0.5f * kterm;
    }
}

// deterministic mean of g_recon[0..B): one block, float4 loads, fixed order
__global__ void reduce_kernel(float* __restrict__ out, int B)
{
    int t = threadIdx.x;                         // 1024 threads
    const float4* g4 = reinterpret_cast<const float4*>(g_recon);
    int n4 = B >> 2;
    float s = 0.f;
    for (int i = t; i < n4; i += 1024) {
        float4 v = g4[i];
        s += (v.x + v.y) + (v.z + v.w);
    }
    #pragma unroll
    for (int d = 16; d > 0; d >>= 1) s += __shfl_xor_sync(FULLMASK, s, d);
    __shared__ float sh[32];
    if ((t & 31) == 0) sh[t >> 5] = s;
    __syncthreads();
    if (t < 32) {
        float v = sh[t];
        #pragma unroll
        for (int d = 16; d > 0; d >>= 1) v += __shfl_xor_sync(FULLMASK, v, d);
        if (t == 0) out[0] = v / (float)B;
    }
}

extern "C" void kernel_launch(void* const* d_in, const int* in_sizes, int n_in,
                              void* d_out, int out_size)
{
    const int*   x   = (const int*)d_in[0];     // (B, 128) int32
    const float* a   = (const float*)d_in[1];   // (B, 65, 7)
    const float* e   = (const float*)d_in[2];   // (B, 64, 4)
    const float* mus = (const float*)d_in[3];   // (B, E)
    const float* lvs = (const float*)d_in[4];   // (B, E)

    int B = in_sizes[1] / 455;                  // (K+1)*7 = 455
    if (B > 8192) B = 8192;
    int E = in_sizes[3] / B;

    int blocks = (B + 7) / 8;                   // 8 batches per 128-thread block
    phmm_fwd_kernel<<<blocks, 128>>>(x, a, e, mus, lvs, B, E);
    reduce_kernel<<<1, 1024>>>((float*)d_out, B);
}